// round 1
// baseline (speedup 1.0000x reference)
#include <cuda_runtime.h>
#include <cuda_bf16.h>

// InverseHadamardTransform: y = FWHT(x) / sqrt(4096) over last axis (n=4096).
// H_4096 = H_16 (x) H_16 (x) H_16  -> 3 register-resident 16-pt transforms,
// 2 shared-memory transposes. Hadamard stages commute, so applying H16 along
// the c, b, a digit axes (i = a*256 + b*16 + c) reproduces the reference's
// 12-stage butterfly exactly.

#define FWHT_N 4096
#define FWHT_THREADS 256

__device__ __forceinline__ void h16(float v[16]) {
#pragma unroll
    for (int h = 1; h < 16; h <<= 1) {
#pragma unroll
        for (int i = 0; i < 16; i++) {
            if (!(i & h)) {
                float a = v[i], b = v[i | h];
                v[i]     = a + b;
                v[i | h] = a - b;
            }
        }
    }
}

__global__ void __launch_bounds__(FWHT_THREADS)
fwht4096_kernel(const float* __restrict__ x, float* __restrict__ out) {
    // Padded layout: phys(a,b,c) = a*272 + b*17 + c  (16*272 floats = 17408 B)
    __shared__ float s[16 * 272];

    const int row = blockIdx.x;
    const float* __restrict__ xr = x + (size_t)row * FWHT_N;
    float* __restrict__ orow     = out + (size_t)row * FWHT_N;

    const int j = threadIdx.x;
    float v[16];

    // ---- Round 1: H16 along c. Thread j=(a,b) holds 16 contiguous elems. ----
    const float4* __restrict__ xv = reinterpret_cast<const float4*>(xr + j * 16);
#pragma unroll
    for (int k = 0; k < 4; k++) {
        float4 t = xv[k];
        v[4 * k + 0] = t.x;
        v[4 * k + 1] = t.y;
        v[4 * k + 2] = t.z;
        v[4 * k + 3] = t.w;
    }
    h16(v);
    {
        const int a = j >> 4, b = j & 15;
        float* base = s + a * 272 + b * 17;
#pragma unroll
        for (int c = 0; c < 16; c++) base[c] = v[c];   // conflict-free (17 odd)
    }
    __syncthreads();

    // ---- Round 2: H16 along b. Thread j=(a,c), stride-17 gather. ----
    {
        const int a = j >> 4, c = j & 15;
        float* base = s + a * 272 + c;
#pragma unroll
        for (int b = 0; b < 16; b++) v[b] = base[b * 17];  // conflict-free
        h16(v);
#pragma unroll
        for (int b = 0; b < 16; b++) base[b * 17] = v[b];
    }
    __syncthreads();

    // ---- Round 3: H16 along a. Thread j=(b,c), stride-272 gather. ----
    {
        const int b = j >> 4, c = j & 15;
        const float* base = s + b * 17 + c;
#pragma unroll
        for (int a = 0; a < 16; a++) v[a] = base[a * 272]; // ~1 two-way pair/access
        h16(v);
        const float scale = 1.0f / 64.0f;  // 1/sqrt(4096)
        // global index = a*256 + b*16 + c = a*256 + j  -> warp-coalesced stores
#pragma unroll
        for (int a = 0; a < 16; a++) orow[a * 256 + j] = v[a] * scale;
    }
}

extern "C" void kernel_launch(void* const* d_in, const int* in_sizes, int n_in,
                              void* d_out, int out_size) {
    const float* x = (const float*)d_in[0];
    float* out     = (float*)d_out;
    const int nrows = in_sizes[0] / FWHT_N;   // 2*8192 = 16384
    fwht4096_kernel<<<nrows, FWHT_THREADS>>>(x, out);
}

// round 4
// speedup vs baseline: 1.1166x; 1.1166x over previous
#include <cuda_runtime.h>
#include <cuda_bf16.h>

// FWHT-4096 / sqrt(4096). Bit-group schedule: index i = Q*1024 + P*128 + D*32 + L
//   (Q: i[10:12], P: i[7:10], D: i[5:7], L: i[0:5])
// Round 1: H32 over A=(Q,P)=i[7:12] in regs  (loads:  lanes = L, ideal coalescing)
// Round 2: H32 over L=i[0:5]        in regs  (via smem transpose, conflict-free)
// Round 3: H4  over D=i[5:7]        in regs  (stores: lanes = L, ideal coalescing)
// All Hadamard bit-stages commute, so this equals the reference 12-stage FWHT.

#define FWHT_N 4096
#define ROW_THREADS 128
#define ROWS_PER_BLOCK 2
#define BLOCK_THREADS (ROW_THREADS * ROWS_PER_BLOCK)
// smem strides: L:1, D:33 (==1 mod 32), P:132 (==4 mod 32), Q:1056 (==0 mod 32)
#define S_D 33
#define S_P 132
#define S_Q 1056
#define S_ROW (4 * S_Q)   // 4224 floats per row

__device__ __forceinline__ void h32(float v[32]) {
#pragma unroll
    for (int h = 1; h < 32; h <<= 1) {
#pragma unroll
        for (int i = 0; i < 32; i++) {
            if (!(i & h)) {
                float a = v[i], b = v[i | h];
                v[i]     = a + b;
                v[i | h] = a - b;
            }
        }
    }
}

__global__ void __launch_bounds__(BLOCK_THREADS, 4)
fwht4096_kernel(const float* __restrict__ x, float* __restrict__ out) {
    __shared__ float s[ROWS_PER_BLOCK * S_ROW];

    const int tid = threadIdx.x;
    const int rib = tid >> 7;          // row in block
    const int j   = tid & 127;         // thread within row: j = D*32 + L at round 1
    const int row = blockIdx.x * ROWS_PER_BLOCK + rib;

    const float* __restrict__ xr = x + (size_t)row * FWHT_N;
    float* __restrict__ orow     = out + (size_t)row * FWHT_N;
    float* __restrict__ sr       = s + rib * S_ROW;

    float v[32];

    // ---- Round 1: regs = A = (Q,P). Load v[r] = x[r*128 + j]; lanes = L. ----
#pragma unroll
    for (int r = 0; r < 32; r++) v[r] = xr[r * 128 + j];
    h32(v);   // transforms index bits 7..11

    // W1: thread (D,L) writes A-indexed values. Lanes vary L -> conflict-free.
    {
        const int D = j >> 5, L = j & 31;
        float* w = sr + D * S_D + L;
#pragma unroll
        for (int r = 0; r < 32; r++) {
            const int Q = r >> 3, P = r & 7;
            w[Q * S_Q + P * S_P] = v[r];
        }
    }
    __syncthreads();

    // ---- Round 2: regs = L. Thread (Q,P,D): j = Q*32 + P*4 + D. ----
    {
        const int D = j & 3, P = (j >> 2) & 7, Q = j >> 5;
        float* b = sr + Q * S_Q + P * S_P + D * S_D;
        // banks = 4P + D + L mod 32: lanes (P,D) cover 0..31 -> conflict-free
#pragma unroll
        for (int L = 0; L < 32; L++) v[L] = b[L];
        h32(v);   // transforms index bits 0..4
#pragma unroll
        for (int L = 0; L < 32; L++) b[L] = v[L];
    }
    __syncthreads();

    // ---- Round 3: regs = (P,D), r = P*4 + D. Thread (Q,L): j = Q*32 + L. ----
    {
        const int L = j & 31, Q = j >> 5;
        const float* b = sr + Q * S_Q + L;
#pragma unroll
        for (int r = 0; r < 32; r++) {
            const int P = r >> 2, D = r & 3;
            v[r] = b[P * S_P + D * S_D];   // lanes vary L -> conflict-free
        }
        // H4 over D = reg bits 0..1 (index bits 5..6); P bits are passengers.
#pragma unroll
        for (int h = 1; h < 4; h <<= 1) {
#pragma unroll
            for (int i = 0; i < 32; i++) {
                if (!(i & h)) {
                    float a = v[i], c = v[i | h];
                    v[i]     = a + c;
                    v[i | h] = a - c;
                }
            }
        }
        const float scale = 1.0f / 64.0f;   // 1/sqrt(4096)
        float* o = orow + Q * 1024 + L;
        // store addr = Q*1024 + P*128 + D*32 + L; lanes = L -> fully coalesced
#pragma unroll
        for (int r = 0; r < 32; r++) {
            const int P = r >> 2, D = r & 3;
            o[P * 128 + D * 32] = v[r] * scale;
        }
    }
}

extern "C" void kernel_launch(void* const* d_in, const int* in_sizes, int n_in,
                              void* d_out, int out_size) {
    const float* x = (const float*)d_in[0];
    float* out     = (float*)d_out;
    const int nrows = in_sizes[0] / FWHT_N;           // 16384
    const int grid  = nrows / ROWS_PER_BLOCK;         // 8192
    fwht4096_kernel<<<grid, BLOCK_THREADS>>>(x, out);
}